// round 6
// baseline (speedup 1.0000x reference)
#include <cuda_runtime.h>
#include <cstdint>

#define N_POINTS_C 1048576
#define N_LEVELS_C 16
#define LOG2_T_C 19
#define T_C (1u << LOG2_T_C)
#define TMASK_C (T_C - 1u)

#define NBUCKETS 32768     // 32^3 spatial buckets, mean 32 points each
#define CAP 64             // slots per bucket
#define MAIN_SLOTS (NBUCKETS * CAP)   // 2097152
#define OVF_CAP 65536

__constant__ int c_res[N_LEVELS_C] = {
    16, 20, 25, 32, 40, 50, 64, 80, 101, 128, 161, 203, 256, 322, 406, 512
};

// Scratch (device globals: allocation-free).
// g_cnt[NBUCKETS] is the overflow counter; zeroed with one memset.
__device__ unsigned int g_cnt[NBUCKETS + 1];
__device__ float4       g_slots[MAIN_SLOTS];  // 32MB bucketed points
__device__ float4       g_ovf[OVF_CAP];       // overflow points

__device__ __forceinline__ int bucket_of(float px, float py, float pz) {
    int bx = (int)(px * 32.0f); bx = bx > 31 ? 31 : (bx < 0 ? 0 : bx);
    int by = (int)(py * 32.0f); by = by > 31 ? 31 : (by < 0 ? 0 : by);
    int bz = (int)(pz * 32.0f); bz = bz > 31 ? 31 : (bz < 0 ? 0 : bz);
    return (bz << 10) | (by << 5) | bx;
}

__global__ void scatter_kernel(const float* __restrict__ x) {
    int n = blockIdx.x * blockDim.x + threadIdx.x;
    if (n >= N_POINTS_C) return;
    float px = x[3 * n + 0], py = x[3 * n + 1], pz = x[3 * n + 2];
    int b = bucket_of(px, py, pz);
    unsigned int pos = atomicAdd(&g_cnt[b], 1u);
    float4 rec = make_float4(px, py, pz, __int_as_float(n));
    if (pos < CAP) {
        g_slots[b * CAP + pos] = rec;
    } else {
        unsigned int o = atomicAdd(&g_cnt[NBUCKETS], 1u);
        if (o < OVF_CAP) g_ovf[o] = rec;
    }
}

// Process levels [L_BEG, L_END) for every bucketed point; write the
// corresponding half of the output row.
template <int L_BEG, int L_END>
__global__ void __launch_bounds__(256, 8) hashgrid_part_kernel(
    const float* __restrict__ emb,
    float* __restrict__ out)
{
    const int t = blockIdx.x * blockDim.x + threadIdx.x;

    float4 p;
    if (t < MAIN_SLOTS) {
        const int b = t >> 6;
        const int s = t & 63;
        unsigned int c = g_cnt[b];     // broadcast within warp
        if (c > CAP) c = CAP;
        if ((unsigned)s >= c) return;
        p = g_slots[t];
    } else {
        unsigned int o = (unsigned)(t - MAIN_SLOTS);
        unsigned int oc = g_cnt[NBUCKETS];
        if (oc > OVF_CAP) oc = OVF_CAP;
        if (o >= oc) return;
        p = g_ovf[o];
    }

    const float px = p.x, py = p.y, pz = p.z;
    const int  oidx = __float_as_int(p.w);

    float4* __restrict__ orow = reinterpret_cast<float4*>(out + (size_t)oidx * 32);

    float accpair[4];

#pragma unroll
    for (int l = L_BEG; l < L_END; l++) {
        const int res = c_res[l];
        const float rf = (float)(res - 1);

        const float sx = px * rf;
        const float sy = py * rf;
        const float sz = pz * rf;

        int fx = (int)sx; fx = fx > res - 2 ? res - 2 : fx; fx = fx < 0 ? 0 : fx;
        int fy = (int)sy; fy = fy > res - 2 ? res - 2 : fy; fy = fy < 0 ? 0 : fy;
        int fz = (int)sz; fz = fz > res - 2 ? res - 2 : fz; fz = fz < 0 ? 0 : fz;

        const float tx = sx - (float)fx;
        const float ty = sy - (float)fy;
        const float tz = sz - (float)fz;
        const float ux = 1.0f - tx;
        const float uy = 1.0f - ty;
        const float uz = 1.0f - tz;

        const unsigned hy0 = (unsigned)fy * 2654435761u;
        const unsigned hy1 = hy0 + 2654435761u;
        const unsigned hz0 = (unsigned)fz * 805459861u;
        const unsigned hz1 = hz0 + 805459861u;

        unsigned mm[4];
        mm[0] = hy0 ^ hz0;
        mm[1] = hy1 ^ hz0;
        mm[2] = hy0 ^ hz1;
        mm[3] = hy1 ^ hz1;

        // x-pair trick: even base e = fx & ~1 -> h(e), h(e+1)=h(e)^1 are one
        // aligned float4. Odd lanes also fetch h(e+2) with a predicated float2.
        const unsigned e   = (unsigned)(fx & ~1);
        const bool     odd = (fx & 1) != 0;

        const float2* __restrict__ tab =
            reinterpret_cast<const float2*>(emb) + (size_t)l * T_C;
        const float4* __restrict__ tab4 =
            reinterpret_cast<const float4*>(tab);

        unsigned he[4], h2[4];
#pragma unroll
        for (int c = 0; c < 4; c++) {
            he[c] = (e ^ mm[c]) & TMASK_C;
            h2[c] = ((e + 2u) ^ mm[c]) & TMASK_C;
        }

        float4 q[4];
#pragma unroll
        for (int c = 0; c < 4; c++) q[c] = __ldg(&tab4[he[c] >> 1]);

        float2 v2[4];
#pragma unroll
        for (int c = 0; c < 4; c++) {
            v2[c] = make_float2(0.0f, 0.0f);
            if (odd) v2[c] = __ldg(&tab[h2[c]]);
        }

        float wyz[4];
        wyz[0] = uy * uz;
        wyz[1] = ty * uz;
        wyz[2] = uy * tz;
        wyz[3] = ty * tz;

        float a0 = 0.0f, a1 = 0.0f;
#pragma unroll
        for (int c = 0; c < 4; c++) {
            float2 ve, ve1;
            if (he[c] & 1u) {
                ve  = make_float2(q[c].z, q[c].w);
                ve1 = make_float2(q[c].x, q[c].y);
            } else {
                ve  = make_float2(q[c].x, q[c].y);
                ve1 = make_float2(q[c].z, q[c].w);
            }
            float2 vx0 = odd ? ve1 : ve;
            float2 vx1 = odd ? v2[c] : ve1;

            const float w0 = ux * wyz[c];
            const float w1 = tx * wyz[c];
            a0 += w0 * vx0.x + w1 * vx1.x;
            a1 += w0 * vx0.y + w1 * vx1.y;
        }

        accpair[2 * (l & 1) + 0] = a0;
        accpair[2 * (l & 1) + 1] = a1;
        if (l & 1) {
            orow[l >> 1] = make_float4(accpair[0], accpair[1],
                                       accpair[2], accpair[3]);
        }
    }
}

extern "C" void kernel_launch(void* const* d_in, const int* in_sizes, int n_in,
                              void* d_out, int out_size)
{
    const float* x = (const float*)d_in[0];
    const float* emb = (const float*)d_in[1];
    float* out = (float*)d_out;

    const int threads = 256;

    void* cnt_ptr = nullptr;
    cudaGetSymbolAddress(&cnt_ptr, g_cnt);
    cudaMemsetAsync(cnt_ptr, 0, (NBUCKETS + 1) * sizeof(unsigned int));

    scatter_kernel<<<(N_POINTS_C + threads - 1) / threads, threads>>>(x);

    const int main_blocks = (MAIN_SLOTS + OVF_CAP) / threads;  // 8448
    hashgrid_part_kernel<0, 8><<<main_blocks, threads>>>(emb, out);
    hashgrid_part_kernel<8, 16><<<main_blocks, threads>>>(emb, out);
}

// round 7
// speedup vs baseline: 1.0556x; 1.0556x over previous
#include <cuda_runtime.h>
#include <cstdint>

#define N_POINTS_C 1048576
#define N_LEVELS_C 16
#define LOG2_T_C 19
#define T_C (1u << LOG2_T_C)
#define TMASK_C (T_C - 1u)

#define NBUCKETS 32768     // 32^3 spatial buckets, mean 32 points each
#define CAP 64             // slots per bucket
#define MAIN_SLOTS (NBUCKETS * CAP)   // 2097152
#define OVF_CAP 65536

__constant__ int c_res[N_LEVELS_C] = {
    16, 20, 25, 32, 40, 50, 64, 80, 101, 128, 161, 203, 256, 322, 406, 512
};

// Scratch (device globals: allocation-free).
// g_cnt[NBUCKETS] is the overflow counter; zeroed with one memset.
__device__ unsigned int g_cnt[NBUCKETS + 1];
__device__ float4       g_slots[MAIN_SLOTS];  // 32MB bucketed points
__device__ float4       g_ovf[OVF_CAP];       // overflow points

__device__ __forceinline__ int bucket_of(float px, float py, float pz) {
    int bx = (int)(px * 32.0f); bx = bx > 31 ? 31 : (bx < 0 ? 0 : bx);
    int by = (int)(py * 32.0f); by = by > 31 ? 31 : (by < 0 ? 0 : by);
    int bz = (int)(pz * 32.0f); bz = bz > 31 ? 31 : (bz < 0 ? 0 : bz);
    return (bz << 10) | (by << 5) | bx;
}

__global__ void scatter_kernel(const float* __restrict__ x) {
    int n = blockIdx.x * blockDim.x + threadIdx.x;
    if (n >= N_POINTS_C) return;
    float px = x[3 * n + 0], py = x[3 * n + 1], pz = x[3 * n + 2];
    int b = bucket_of(px, py, pz);
    unsigned int pos = atomicAdd(&g_cnt[b], 1u);
    float4 rec = make_float4(px, py, pz, __int_as_float(n));
    if (pos < CAP) {
        g_slots[b * CAP + pos] = rec;
    } else {
        unsigned int o = atomicAdd(&g_cnt[NBUCKETS], 1u);
        if (o < OVF_CAP) g_ovf[o] = rec;
    }
}

__global__ void __launch_bounds__(256, 8) hashgrid_kernel(
    const float* __restrict__ emb,
    float* __restrict__ out)
{
    const int t = blockIdx.x * blockDim.x + threadIdx.x;

    float4 p;
    if (t < MAIN_SLOTS) {
        const int b = t >> 6;
        const int s = t & 63;
        unsigned int c = g_cnt[b];     // broadcast within warp
        if (c > CAP) c = CAP;
        if ((unsigned)s >= c) return;
        p = g_slots[t];
    } else {
        unsigned int o = (unsigned)(t - MAIN_SLOTS);
        unsigned int oc = g_cnt[NBUCKETS];
        if (oc > OVF_CAP) oc = OVF_CAP;
        if (o >= oc) return;
        p = g_ovf[o];
    }

    const float px = p.x, py = p.y, pz = p.z;
    const int  oidx = __float_as_int(p.w);

    float4* __restrict__ orow = reinterpret_cast<float4*>(out + (size_t)oidx * 32);

    float accpair[4];   // 2 levels' worth, flushed every 2 levels

#pragma unroll
    for (int l = 0; l < N_LEVELS_C; l++) {
        const int res = c_res[l];
        const float rf = (float)(res - 1);

        const float sx = px * rf;
        const float sy = py * rf;
        const float sz = pz * rf;

        int fx = (int)sx; fx = fx > res - 2 ? res - 2 : fx; fx = fx < 0 ? 0 : fx;
        int fy = (int)sy; fy = fy > res - 2 ? res - 2 : fy; fy = fy < 0 ? 0 : fy;
        int fz = (int)sz; fz = fz > res - 2 ? res - 2 : fz; fz = fz < 0 ? 0 : fz;

        const float tx = sx - (float)fx;
        const float ty = sy - (float)fy;
        const float tz = sz - (float)fz;
        const float ux = 1.0f - tx;
        const float uy = 1.0f - ty;
        const float uz = 1.0f - tz;

        const unsigned hy0 = (unsigned)fy * 2654435761u;
        const unsigned hy1 = hy0 + 2654435761u;
        const unsigned hz0 = (unsigned)fz * 805459861u;
        const unsigned hz1 = hz0 + 805459861u;

        // x-pair trick: even base e = fx & ~1 -> h(e), h(e+1)=h(e)^1 are one
        // aligned float4. Odd lanes also fetch h(e+2) with a predicated float2.
        const unsigned e   = (unsigned)(fx & ~1);
        const bool     odd = (fx & 1) != 0;

        const float2* __restrict__ tab =
            reinterpret_cast<const float2*>(emb) + (size_t)l * T_C;
        const float4* __restrict__ tab4 =
            reinterpret_cast<const float4*>(tab);

        const float wx0 = ux, wx1 = tx;

        float a0 = 0.0f, a1 = 0.0f;

        // Process the 4 (y,z) corner-pairs in 2 groups of 2 to bound live
        // registers (2 float4 + 2 float2 gathers in flight per group).
#pragma unroll
        for (int g = 0; g < 2; g++) {
            const unsigned hz = (g == 0) ? hz0 : hz1;
            const float    wz = (g == 0) ? uz : tz;

            const unsigned m0 = hy0 ^ hz;
            const unsigned m1 = hy1 ^ hz;

            const unsigned he0 = (e ^ m0) & TMASK_C;
            const unsigned he1 = (e ^ m1) & TMASK_C;
            const unsigned h20 = ((e + 2u) ^ m0) & TMASK_C;
            const unsigned h21 = ((e + 2u) ^ m1) & TMASK_C;

            float4 q0 = __ldg(&tab4[he0 >> 1]);
            float4 q1 = __ldg(&tab4[he1 >> 1]);

            float2 v20 = make_float2(0.0f, 0.0f);
            float2 v21 = make_float2(0.0f, 0.0f);
            if (odd) {
                v20 = __ldg(&tab[h20]);
                v21 = __ldg(&tab[h21]);
            }

#pragma unroll
            for (int k = 0; k < 2; k++) {
                const unsigned he = k ? he1 : he0;
                const float4   q  = k ? q1 : q0;
                const float2   v2 = k ? v21 : v20;
                const float    wy = k ? ty : uy;

                float2 ve, ve1;
                if (he & 1u) {
                    ve  = make_float2(q.z, q.w);
                    ve1 = make_float2(q.x, q.y);
                } else {
                    ve  = make_float2(q.x, q.y);
                    ve1 = make_float2(q.z, q.w);
                }
                float2 vx0 = odd ? ve1 : ve;
                float2 vx1 = odd ? v2  : ve1;

                const float wyz = wy * wz;
                const float w0 = wx0 * wyz;
                const float w1 = wx1 * wyz;
                a0 += w0 * vx0.x + w1 * vx1.x;
                a1 += w0 * vx0.y + w1 * vx1.y;
            }
        }

        accpair[2 * (l & 1) + 0] = a0;
        accpair[2 * (l & 1) + 1] = a1;
        if (l & 1) {
            orow[l >> 1] = make_float4(accpair[0], accpair[1],
                                       accpair[2], accpair[3]);
        }
    }
}

extern "C" void kernel_launch(void* const* d_in, const int* in_sizes, int n_in,
                              void* d_out, int out_size)
{
    const float* x = (const float*)d_in[0];
    const float* emb = (const float*)d_in[1];
    float* out = (float*)d_out;

    const int threads = 256;

    void* cnt_ptr = nullptr;
    cudaGetSymbolAddress(&cnt_ptr, g_cnt);
    cudaMemsetAsync(cnt_ptr, 0, (NBUCKETS + 1) * sizeof(unsigned int));

    scatter_kernel<<<(N_POINTS_C + threads - 1) / threads, threads>>>(x);

    const int main_blocks = (MAIN_SLOTS + OVF_CAP) / threads;  // 8448
    hashgrid_kernel<<<main_blocks, threads>>>(emb, out);
}